// round 14
// baseline (speedup 1.0000x reference)
#include <cuda_runtime.h>
#include <cuda_bf16.h>
#include <cstdint>

#define F 26
#define D 128
#define NROWS 100000
#define B 4096
#define T (B * 20)

// ---- software-pipelined register gather ------------------------------------
// Lane l owns the l-th float4 of each 512B row. Stages of 4 rows, manually
// double-buffered: while stage k is accumulated, stage k+1's LDG.128s are in
// flight. No smem roundtrip (half the L1 wavefronts of cp.async+LDS), no
// scoreboard serialization (unlike naive LDG batches).
__device__ __forceinline__ void gather_accum_pipe(
    const int* __restrict__ vals, int lo, int hi,
    const float4* __restrict__ tab, int lane,
    float4& a0, float4& a1)
{
    const int n = hi - lo;
    const int nst = (n + 3) >> 2;

    int myidx = (lo + lane < hi) ? __ldg(vals + lo + lane) : 0;
    int blk = 0;   // myidx covers rows [32*blk, 32*blk+32) relative to lo

    // prologue: issue stage 0
    float4 v0, v1, v2, v3;
    int cnt = min(4, n);
    {
        int r0 = __shfl_sync(0xffffffffu, myidx, 0);
        int r1 = __shfl_sync(0xffffffffu, myidx, 1);
        int r2 = __shfl_sync(0xffffffffu, myidx, 2);
        int r3 = __shfl_sync(0xffffffffu, myidx, 3);
        v0 = __ldg(tab + (size_t)(unsigned)r0 * 32 + lane);
        if (cnt > 1) v1 = __ldg(tab + (size_t)(unsigned)r1 * 32 + lane);
        if (cnt > 2) v2 = __ldg(tab + (size_t)(unsigned)r2 * 32 + lane);
        if (cnt > 3) v3 = __ldg(tab + (size_t)(unsigned)r3 * 32 + lane);
    }

    for (int st = 0; st < nst; ++st) {
        // issue stage st+1 BEFORE consuming stage st
        float4 w0, w1, w2, w3;
        int ncnt = 0;
        const int nbase = (st + 1) << 2;
        if (nbase < n) {
            if ((nbase >> 5) != blk) {          // crossed a 32-index block
                blk = nbase >> 5;
                const int p = lo + (blk << 5) + lane;
                myidx = (p < hi) ? __ldg(vals + p) : 0;
            }
            ncnt = min(4, n - nbase);
            const int sl = nbase & 31;
            int r0 = __shfl_sync(0xffffffffu, myidx, sl + 0);
            int r1 = __shfl_sync(0xffffffffu, myidx, sl + 1);
            int r2 = __shfl_sync(0xffffffffu, myidx, sl + 2);
            int r3 = __shfl_sync(0xffffffffu, myidx, sl + 3);
            w0 = __ldg(tab + (size_t)(unsigned)r0 * 32 + lane);
            if (ncnt > 1) w1 = __ldg(tab + (size_t)(unsigned)r1 * 32 + lane);
            if (ncnt > 2) w2 = __ldg(tab + (size_t)(unsigned)r2 * 32 + lane);
            if (ncnt > 3) w3 = __ldg(tab + (size_t)(unsigned)r3 * 32 + lane);
        }

        // consume stage st (its loads were issued one iteration ago)
        a0.x += v0.x; a0.y += v0.y; a0.z += v0.z; a0.w += v0.w;
        if (cnt > 1) { a1.x += v1.x; a1.y += v1.y; a1.z += v1.z; a1.w += v1.w; }
        if (cnt > 2) { a0.x += v2.x; a0.y += v2.y; a0.z += v2.z; a0.w += v2.w; }
        if (cnt > 3) { a1.x += v3.x; a1.y += v3.y; a1.z += v3.z; a1.w += v3.w; }

        v0 = w0; v1 = w1; v2 = w2; v3 = w3;
        cnt = ncnt;
    }
}

// ---- fused, sum-split kernel ------------------------------------------------
// Block = 4 warps = 4 consecutive bags of one feature. Offsets are cumulative,
// so the 4 bags occupy ONE contiguous range of vals, split EVENLY over the 4
// warps (crossing bag boundaries) -> zero intra-block imbalance. Per-bag
// partials combine via smem atomicAdd; warp w writes bag w.
__global__ __launch_bounds__(128, 8) void ebag_fused(
    const float* __restrict__ tables,   // [F, NROWS, D]
    const int* __restrict__ values,     // [F, T]
    const int* __restrict__ offsets,    // [F, B+1]
    float* __restrict__ out)            // [B, F, D]
{
    __shared__ __align__(16) float part[4][128]; // 2KB: per-bag partial sums

    const int lane = threadIdx.x & 31;
    const int warp = threadIdx.x >> 5;
    const int f    = blockIdx.y;
    const int bag0 = blockIdx.x * 4;

    const int* offs = offsets + f * (B + 1);
    // 5 boundary offsets held warp-wide in one register, fetched via shfl.
    int off_l = 0;
    if (lane < 5) off_l = __ldg(offs + bag0 + lane);

    // zero the partial buffer (128 threads x 4 floats = all 512 floats)
    reinterpret_cast<float4*>(&part[0][0])[threadIdx.x] =
        make_float4(0.f, 0.f, 0.f, 0.f);
    __syncthreads();

    const int S = __shfl_sync(0xffffffffu, off_l, 0);
    const int E = __shfl_sync(0xffffffffu, off_l, 4);
    const int total = E - S;

    const int* vals = values + (size_t)f * T;
    const float4* tab = reinterpret_cast<const float4*>(
        tables + (size_t)f * NROWS * D);

    // this warp's even share of the concatenated range
    const int lo = S + (int)(((long long)total * warp) >> 2);
    const int hi = S + (int)(((long long)total * (warp + 1)) >> 2);

    if (lo < hi) {
        // find first bag j containing lo: largest j with offs[j] <= lo
        int j = 0;
        int oj1 = __shfl_sync(0xffffffffu, off_l, 1);
        while (j < 3 && oj1 <= lo) {
            ++j;
            oj1 = __shfl_sync(0xffffffffu, off_l, j + 1);
        }

        int p = lo;
        while (p < hi) {
            const int ce = min(hi, oj1);        // chunk end within bag j
            if (ce > p) {
                float4 a0 = make_float4(0.f, 0.f, 0.f, 0.f);
                float4 a1 = make_float4(0.f, 0.f, 0.f, 0.f);
                gather_accum_pipe(vals, p, ce, tab, lane, a0, a1);
                float* pj = &part[j][lane * 4];
                atomicAdd(pj + 0, a0.x + a1.x);
                atomicAdd(pj + 1, a0.y + a1.y);
                atomicAdd(pj + 2, a0.z + a1.z);
                atomicAdd(pj + 3, a0.w + a1.w);
                p = ce;
            }
            if (p >= hi) break;
            ++j;
            oj1 = __shfl_sync(0xffffffffu, off_l, j + 1);
        }
    }
    __syncthreads();

    // warp w writes bag w (always: empty bags must be 0, d_out is poisoned)
    float4 res = reinterpret_cast<const float4*>(&part[warp][0])[lane];
    float4* o = reinterpret_cast<float4*>(out) + ((size_t)(bag0 + warp) * F + f) * 32;
    o[lane] = res;
}

extern "C" void kernel_launch(void* const* d_in, const int* in_sizes, int n_in,
                              void* d_out, int out_size) {
    const float* tables  = (const float*)d_in[0];
    const int*   values  = (const int*)d_in[1];
    const int*   offsets = (const int*)d_in[2];
    float* out = (float*)d_out;

    dim3 grid(B / 4, F);   // feature on y: blocks of one feature grouped -> L2 reuse
    dim3 block(128);       // 4 warps, 4 bags, sum-split evenly
    ebag_fused<<<grid, block>>>(tables, values, offsets, out);
}

// round 15
// speedup vs baseline: 1.3163x; 1.3163x over previous
#include <cuda_runtime.h>
#include <cuda_bf16.h>
#include <cstdint>

#define F 26
#define D 128
#define NROWS 100000
#define B 4096
#define T (B * 20)

// ---- per-warp gather pipeline ---------------------------------------------
// Lane l owns the l-th float4 (16B) of each 512B row. Rows go global->shared
// via cp.async, stages of 4 rows, double buffered (8 slots = 4KB per warp).
__device__ __forceinline__ float4 gather_accum(
    const int* __restrict__ vals, int lo, int hi,
    const char* __restrict__ tabb, uint32_t sb0,
    int lane, const float4* __restrict__ bufw)
{
    float4 a0 = make_float4(0.f, 0.f, 0.f, 0.f);
    float4 a1 = make_float4(0.f, 0.f, 0.f, 0.f);

    for (int base = lo; base < hi; base += 32) {
        const int n = min(32, hi - base);
        int myidx = 0;
        if (base + lane < hi) myidx = __ldg(vals + base + lane);

        const int nstage = (n + 3) >> 2;
        int sbuf = 0;
        int prevcnt = 0;

        for (int st = 0; st < nstage; ++st) {
            const int cnt = min(4, n - st * 4);
            #pragma unroll
            for (int q = 0; q < 4; ++q) {
                if (q < cnt) {
                    int r = __shfl_sync(0xffffffffu, myidx, st * 4 + q);
                    const char* src = tabb + ((size_t)(unsigned)r << 9) + (lane << 4);
                    uint32_t dst = sb0 + (uint32_t)((sbuf * 4 + q) << 9);
                    asm volatile("cp.async.cg.shared.global [%0], [%1], 16;\n"
                                 :: "r"(dst), "l"(src));
                }
            }
            asm volatile("cp.async.commit_group;\n");

            if (st > 0) {
                asm volatile("cp.async.wait_group 1;\n");
                const int pb = (sbuf ^ 1) * 4;
                #pragma unroll
                for (int q = 0; q < 4; ++q) {
                    if (q < prevcnt) {
                        float4 v = bufw[(pb + q) * 32 + lane];
                        if (q & 1) { a1.x += v.x; a1.y += v.y; a1.z += v.z; a1.w += v.w; }
                        else       { a0.x += v.x; a0.y += v.y; a0.z += v.z; a0.w += v.w; }
                    }
                }
            }
            prevcnt = cnt;
            sbuf ^= 1;
        }

        if (nstage > 0) {
            asm volatile("cp.async.wait_group 0;\n");
            const int pb = (sbuf ^ 1) * 4;
            #pragma unroll
            for (int q = 0; q < 4; ++q) {
                if (q < prevcnt) {
                    float4 v = bufw[(pb + q) * 32 + lane];
                    if (q & 1) { a1.x += v.x; a1.y += v.y; a1.z += v.z; a1.w += v.w; }
                    else       { a0.x += v.x; a0.y += v.y; a0.z += v.z; a0.w += v.w; }
                }
            }
        }
    }

    float4 acc;
    acc.x = a0.x + a1.x; acc.y = a0.y + a1.y;
    acc.z = a0.z + a1.z; acc.w = a0.w + a1.w;
    return acc;
}

// ---- fused, sum-split kernel ----------------------------------------------
// Block = 8 warps = 8 consecutive bags of one feature. Offsets are cumulative,
// so the 8 bags occupy ONE contiguous range of vals, split EVENLY over the 8
// warps (crossing bag boundaries) -> zero intra-block imbalance.
// Per-bag partials combine via smem atomicAdd in COMPONENT-MAJOR layout
// part[j][c][lane]: every ATOMS instruction hits bank==lane -> conflict-free
// (4x fewer smem wavefronts than the lane-major float4 layout).
__global__ __launch_bounds__(256, 6) void ebag_fused(
    const float* __restrict__ tables,   // [F, NROWS, D]
    const int* __restrict__ values,     // [F, T]
    const int* __restrict__ offsets,    // [F, B+1]
    float* __restrict__ out)            // [B, F, D]
{
    __shared__ float4 buf[8][8][32];            // 32KB: per-warp pipeline rings
    __shared__ float part[8][4][32];            // 4KB: per-bag partials, comp-major

    const int lane = threadIdx.x & 31;
    const int warp = threadIdx.x >> 5;
    const int f    = blockIdx.y;
    const int bag0 = blockIdx.x * 8;

    const int* offs = offsets + f * (B + 1);
    // 9 boundary offsets held warp-wide in one register, fetched via shfl.
    int off_l = 0;
    if (lane < 9) off_l = __ldg(offs + bag0 + lane);

    // zero the partial buffer (256 threads x 4 floats = 1024 floats)
    reinterpret_cast<float4*>(&part[0][0][0])[threadIdx.x] =
        make_float4(0.f, 0.f, 0.f, 0.f);
    __syncthreads();

    const int S = __shfl_sync(0xffffffffu, off_l, 0);
    const int E = __shfl_sync(0xffffffffu, off_l, 8);
    const int total = E - S;

    const int* vals = values + (size_t)f * T;
    const char* tabb = reinterpret_cast<const char*>(
        tables + (size_t)f * NROWS * D);
    uint32_t sb0 = (uint32_t)__cvta_generic_to_shared(&buf[warp][0][lane]);

    // this warp's even share of the concatenated range
    int lo = S + (int)(((long long)total * warp) >> 3);
    int hi = S + (int)(((long long)total * (warp + 1)) >> 3);

    if (lo < hi) {
        // find first bag j containing lo: largest j with offs[j] <= lo
        int j = 0;
        int oj1 = __shfl_sync(0xffffffffu, off_l, 1);
        while (j < 7) {
            if (oj1 > lo) break;
            ++j;
            oj1 = __shfl_sync(0xffffffffu, off_l, j + 1);
        }

        int p = lo;
        while (p < hi) {
            const int ce = min(hi, oj1);        // chunk end within bag j
            if (ce > p) {
                float4 acc = gather_accum(vals, p, ce, tabb, sb0, lane,
                                          &buf[warp][0][0]);
                // conflict-free: bank == lane for every component
                atomicAdd(&part[j][0][lane], acc.x);
                atomicAdd(&part[j][1][lane], acc.y);
                atomicAdd(&part[j][2][lane], acc.z);
                atomicAdd(&part[j][3][lane], acc.w);
                p = ce;
            }
            if (p >= hi) break;
            ++j;
            oj1 = __shfl_sync(0xffffffffu, off_l, j + 1);
        }
    }
    __syncthreads();

    // warp w writes bag w (always: empty bags must be 0, d_out is poisoned)
    float4 res;
    res.x = part[warp][0][lane];
    res.y = part[warp][1][lane];
    res.z = part[warp][2][lane];
    res.w = part[warp][3][lane];
    float4* o = reinterpret_cast<float4*>(out) + ((size_t)(bag0 + warp) * F + f) * 32;
    o[lane] = res;
}

extern "C" void kernel_launch(void* const* d_in, const int* in_sizes, int n_in,
                              void* d_out, int out_size) {
    const float* tables  = (const float*)d_in[0];
    const int*   values  = (const int*)d_in[1];
    const int*   offsets = (const int*)d_in[2];
    float* out = (float*)d_out;

    dim3 grid(B / 8, F);   // feature on y: blocks of one feature grouped -> L2 reuse
    dim3 block(256);       // 8 warps, 8 bags, sum-split evenly
    ebag_fused<<<grid, block>>>(tables, values, offsets, out);
}